// round 6
// baseline (speedup 1.0000x reference)
#include <cuda_runtime.h>
#include <cuda_bf16.h>

// DynamicUpsamplingFilter: out[b,c,h,w] = sum_{dy,dx} x[b,c,h+dy-1,w+dx-1] * filters[b,dy*3+dx,h,w]
// x [4,128,180,320] f32, filters [4,9,180,320] f32, out [4,128,180,320] f32.
//
// R6: 2x2 output patch per thread (rows h0,h0+1 x pixels w,w+1). Loads 4
// input rows per channel instead of 6 -> ~30% fewer L1 wavefronts per output
// (row redundancy 3x -> 2x; middle rows reused from registers for both
// output rows). Staged unroll U=2 keeps 24 independent LDGs (~40 distinct
// 128B lines) per stall region. Filters for both rows stay register-resident
// (36 regs); launch_bounds(256,2) to avoid spill.

#define B_ 4
#define C_ 128
#define H_ 180
#define W_ 320
#define CPB 16           // channels per block (grid.y = 8)
#define TPB 256
#define U   2            // channel unroll (staged)

__global__ __launch_bounds__(TPB, 2)
void duf_kernel(const float* __restrict__ x,
                const float* __restrict__ filters,
                float* __restrict__ out)
{
    const int HW = H_ * W_;
    int tid = blockIdx.x * TPB + threadIdx.x;
    const int WH = W_ / 2;             // 160 pixel-pairs per row
    int wh = tid % WH;
    int t2 = tid / WH;
    int rh = t2 % (H_ / 2);            // row-pair index, 90
    int b  = t2 / (H_ / 2);
    int w  = wh * 2;
    int h0 = rh * 2;
    int h1 = h0 + 1;

    int c0 = blockIdx.y * CPB;

    // ---- filters for both output rows: 9 taps x float2 x 2 rows ----
    const float* fbase = filters + ((size_t)b * 9) * HW + w;
    float2 fA[9], fB[9];
#pragma unroll
    for (int i = 0; i < 9; i++) {
        fA[i] = __ldg((const float2*)(fbase + (size_t)i * HW + (size_t)h0 * W_));
        fB[i] = __ldg((const float2*)(fbase + (size_t)i * HW + (size_t)h1 * W_));
    }

    // ---- boundary masks folded into coefficients ----
    // h0 is even (never H-1); h1 is odd (never 0). H=180.
    if (h0 == 0) {                       // row0's dy=0 taps use rm
        fA[0] = make_float2(0.f, 0.f);
        fA[1] = make_float2(0.f, 0.f);
        fA[2] = make_float2(0.f, 0.f);
    }
    if (h1 == H_ - 1) {                  // row1's dy=2 taps use rp
        fB[6] = make_float2(0.f, 0.f);
        fB[7] = make_float2(0.f, 0.f);
        fB[8] = make_float2(0.f, 0.f);
    }
    if (w == 0) {                        // pixel0 left taps
        fA[0].x = 0.f; fA[3].x = 0.f; fA[6].x = 0.f;
        fB[0].x = 0.f; fB[3].x = 0.f; fB[6].x = 0.f;
    }
    if (w + 2 == W_) {                   // pixel1 right taps
        fA[2].y = 0.f; fA[5].y = 0.f; fA[8].y = 0.f;
        fB[2].y = 0.f; fB[5].y = 0.f; fB[8].y = 0.f;
    }

    // clamped offsets (clamped values multiplied by zeroed coefficients)
    int hm  = (h0 > 0)      ? h0 - 1 : 0;     // row above h0
    int hp  = (h1 < H_ - 1) ? h1 + 1 : h1;    // row below h1
    int wl2 = (w >= 2)      ? w - 2 : 0;      // float2 covering [w-2, w-1]
    int ws  = (w + 2 < W_)  ? w + 2 : W_ - 1; // scalar x(w+2)

    const float* base = x + ((size_t)(b * C_ + c0)) * HW;
    const float* pm = base + (size_t)hm * W_;
    const float* p0 = base + (size_t)h0 * W_;
    const float* p1 = base + (size_t)h1 * W_;
    const float* pp = base + (size_t)hp * W_;
    float* po0 = out + (((size_t)(b * C_ + c0)) * H_ + h0) * (size_t)W_ + w;
    float* po1 = po0 + W_;

    for (int c = 0; c < CPB; c += U) {
        float2 vm[U], lm[U], v0[U], l0[U], v1[U], l1[U], vp[U], lp[U];
        float  sm[U], s0[U], s1[U], sp[U];

        // ---- phase 1: 12*U independent contiguous loads ----
#pragma unroll
        for (int u = 0; u < U; u++) {
            const float* qm = pm + (size_t)u * HW;
            const float* q0 = p0 + (size_t)u * HW;
            const float* q1 = p1 + (size_t)u * HW;
            const float* qp = pp + (size_t)u * HW;
            vm[u] = __ldg((const float2*)(qm + w));
            lm[u] = __ldg((const float2*)(qm + wl2));
            sm[u] = __ldg(qm + ws);
            v0[u] = __ldg((const float2*)(q0 + w));
            l0[u] = __ldg((const float2*)(q0 + wl2));
            s0[u] = __ldg(q0 + ws);
            v1[u] = __ldg((const float2*)(q1 + w));
            l1[u] = __ldg((const float2*)(q1 + wl2));
            s1[u] = __ldg(q1 + ws);
            vp[u] = __ldg((const float2*)(qp + w));
            lp[u] = __ldg((const float2*)(qp + wl2));
            sp[u] = __ldg(qp + ws);
        }

        // ---- phase 2: compute + store (rows r0,r1 reused for both outputs) ----
#pragma unroll
        for (int u = 0; u < U; u++) {
            float2 accA;   // output row h0: taps rm, r0, r1
            accA.x = fA[0].x*lm[u].y + fA[1].x*vm[u].x + fA[2].x*vm[u].y
                   + fA[3].x*l0[u].y + fA[4].x*v0[u].x + fA[5].x*v0[u].y
                   + fA[6].x*l1[u].y + fA[7].x*v1[u].x + fA[8].x*v1[u].y;
            accA.y = fA[0].y*vm[u].x + fA[1].y*vm[u].y + fA[2].y*sm[u]
                   + fA[3].y*v0[u].x + fA[4].y*v0[u].y + fA[5].y*s0[u]
                   + fA[6].y*v1[u].x + fA[7].y*v1[u].y + fA[8].y*s1[u];

            float2 accB;   // output row h1: taps r0, r1, rp
            accB.x = fB[0].x*l0[u].y + fB[1].x*v0[u].x + fB[2].x*v0[u].y
                   + fB[3].x*l1[u].y + fB[4].x*v1[u].x + fB[5].x*v1[u].y
                   + fB[6].x*lp[u].y + fB[7].x*vp[u].x + fB[8].x*vp[u].y;
            accB.y = fB[0].y*v0[u].x + fB[1].y*v0[u].y + fB[2].y*s0[u]
                   + fB[3].y*v1[u].x + fB[4].y*v1[u].y + fB[5].y*s1[u]
                   + fB[6].y*vp[u].x + fB[7].y*vp[u].y + fB[8].y*sp[u];

            *((float2*)(po0 + (size_t)u * HW)) = accA;
            *((float2*)(po1 + (size_t)u * HW)) = accB;
        }

        pm += (size_t)U * HW;
        p0 += (size_t)U * HW;
        p1 += (size_t)U * HW;
        pp += (size_t)U * HW;
        po0 += (size_t)U * HW;
        po1 += (size_t)U * HW;
    }
}

extern "C" void kernel_launch(void* const* d_in, const int* in_sizes, int n_in,
                              void* d_out, int out_size)
{
    const float* x       = (const float*)d_in[0];
    const float* filters = (const float*)d_in[1];
    float* out           = (float*)d_out;

    int spatial_threads = B_ * (H_ / 2) * (W_ / 2);   // 57600
    dim3 grid(spatial_threads / TPB, C_ / CPB);       // (225, 8) = 1800 blocks
    duf_kernel<<<grid, TPB>>>(x, filters, out);
}

// round 7
// speedup vs baseline: 1.1808x; 1.1808x over previous
#include <cuda_runtime.h>
#include <cuda_bf16.h>

// DynamicUpsamplingFilter: out[b,c,h,w] = sum_{dy,dx} x[b,c,h+dy-1,w+dx-1] * filters[b,dy*3+dx,h,w]
// x [4,128,180,320] f32, filters [4,9,180,320] f32, out [4,128,180,320] f32.
//
// R7: 4 pixels/thread (float4 main loads) + R5's staged unroll-4. 9 LDGs per
// channel-iter now cover 4 outputs (was 2) -> LSU instr floor halves; staged
// batch = 36 LDGs (~48 distinct main 128B lines) per warp per stall region.
// Halos are scalar loads at w-1 / w+4 (L1 hits on neighbors' main lines).
// Boundary handling hoisted into zeroed filter coefficients + clamped offsets;
// hot loop branch-free.

#define B_ 4
#define C_ 128
#define H_ 180
#define W_ 320
#define CPB 16           // channels per block (grid.y = 8)
#define TPB 256
#define U   4            // channel unroll (staged)

__global__ __launch_bounds__(TPB, 2)
void duf_kernel(const float* __restrict__ x,
                const float* __restrict__ filters,
                float* __restrict__ out)
{
    const int HW = H_ * W_;
    int tid = blockIdx.x * TPB + threadIdx.x;
    const int WQ = W_ / 4;             // 80 pixel-quads per row
    int wq = tid % WQ;
    int t2 = tid / WQ;
    int h  = t2 % H_;
    int b  = t2 / H_;
    int w  = wq * 4;

    int c0 = blockIdx.y * CPB;

    // ---- 9 filter float4s (tap i, pixels w..w+3) ----
    const float* fb = filters + ((size_t)b * 9) * HW + (size_t)h * W_ + w;
    float4 f[9];
#pragma unroll
    for (int i = 0; i < 9; i++)
        f[i] = __ldg((const float4*)(fb + (size_t)i * HW));

    // ---- boundary masking folded into coefficients ----
    if (h == 0) {
        f[0] = make_float4(0,0,0,0);
        f[1] = make_float4(0,0,0,0);
        f[2] = make_float4(0,0,0,0);
    }
    if (h == H_ - 1) {
        f[6] = make_float4(0,0,0,0);
        f[7] = make_float4(0,0,0,0);
        f[8] = make_float4(0,0,0,0);
    }
    if (w == 0) {                  // pixel0 left taps off the edge
        f[0].x = 0.f; f[3].x = 0.f; f[6].x = 0.f;
    }
    if (w + 4 == W_) {             // pixel3 right taps off the edge
        f[2].w = 0.f; f[5].w = 0.f; f[8].w = 0.f;
    }

    // clamped offsets (clamped values hit zeroed coefficients)
    int hm = (h > 0)      ? h - 1 : 0;
    int hp = (h < H_ - 1) ? h + 1 : h;
    int wl = (w > 0)      ? w - 1 : 0;        // scalar x(w-1)
    int wr = (w + 4 < W_) ? w + 4 : W_ - 1;   // scalar x(w+4)

    const float* base = x + ((size_t)(b * C_ + c0)) * HW;
    const float* pm = base + (size_t)hm * W_;
    const float* p0 = base + (size_t)h  * W_;
    const float* pp = base + (size_t)hp * W_;
    float* po = out + (((size_t)(b * C_ + c0)) * H_ + h) * (size_t)W_ + w;

    for (int c = 0; c < CPB; c += U) {
        float4 vm[U], v0[U], vp[U];
        float  ml[U], mr[U], zl[U], zr[U], pl[U], pr[U];

        // ---- phase 1: 9*U independent loads, front-batched ----
#pragma unroll
        for (int u = 0; u < U; u++) {
            const float* qm = pm + (size_t)u * HW;
            const float* q0 = p0 + (size_t)u * HW;
            const float* qp = pp + (size_t)u * HW;
            vm[u] = __ldg((const float4*)(qm + w));
            ml[u] = __ldg(qm + wl);
            mr[u] = __ldg(qm + wr);
            v0[u] = __ldg((const float4*)(q0 + w));
            zl[u] = __ldg(q0 + wl);
            zr[u] = __ldg(q0 + wr);
            vp[u] = __ldg((const float4*)(qp + w));
            pl[u] = __ldg(qp + wl);
            pr[u] = __ldg(qp + wr);
        }

        // ---- phase 2: compute + store ----
#pragma unroll
        for (int u = 0; u < U; u++) {
            float4 acc;
            acc.x = f[0].x*ml[u]   + f[1].x*vm[u].x + f[2].x*vm[u].y
                  + f[3].x*zl[u]   + f[4].x*v0[u].x + f[5].x*v0[u].y
                  + f[6].x*pl[u]   + f[7].x*vp[u].x + f[8].x*vp[u].y;
            acc.y = f[0].y*vm[u].x + f[1].y*vm[u].y + f[2].y*vm[u].z
                  + f[3].y*v0[u].x + f[4].y*v0[u].y + f[5].y*v0[u].z
                  + f[6].y*vp[u].x + f[7].y*vp[u].y + f[8].y*vp[u].z;
            acc.z = f[0].z*vm[u].y + f[1].z*vm[u].z + f[2].z*vm[u].w
                  + f[3].z*v0[u].y + f[4].z*v0[u].z + f[5].z*v0[u].w
                  + f[6].z*vp[u].y + f[7].z*vp[u].z + f[8].z*vp[u].w;
            acc.w = f[0].w*vm[u].z + f[1].w*vm[u].w + f[2].w*mr[u]
                  + f[3].w*v0[u].z + f[4].w*v0[u].w + f[5].w*zr[u]
                  + f[6].w*vp[u].z + f[7].w*vp[u].w + f[8].w*pr[u];

            *((float4*)(po + (size_t)u * HW)) = acc;
        }

        pm += (size_t)U * HW;
        p0 += (size_t)U * HW;
        pp += (size_t)U * HW;
        po += (size_t)U * HW;
    }
}

extern "C" void kernel_launch(void* const* d_in, const int* in_sizes, int n_in,
                              void* d_out, int out_size)
{
    const float* x       = (const float*)d_in[0];
    const float* filters = (const float*)d_in[1];
    float* out           = (float*)d_out;

    int spatial_threads = B_ * H_ * (W_ / 4);     // 57600
    dim3 grid(spatial_threads / TPB, C_ / CPB);   // (225, 8) = 1800 blocks
    duf_kernel<<<grid, TPB>>>(x, filters, out);
}